// round 6
// baseline (speedup 1.0000x reference)
#include <cuda_runtime.h>

// out[b,i,h,w] = sum_j x[b,j,h,w] - x[b,i,h,w]
// x: fp32 [16, 256, 128, 128]
//
// R6: persistent software-pipelined kernel.
//  - 444 blocks (3/SM) x 256 threads, grid-stride over 8192 tiles.
//  - Each tile: 32 channel-groups x 8 float4 lanes, CPT=8 channels/thread.
//  - Loads for tile t+1 are issued BEFORE the reduce/store of tile t
//    (double-buffered registers), so the scoreboard wait on loads is hidden
//    by a full iteration and loads/stores continuously coexist at HBM.
//  - Ping-pong smem reduction buffers -> one __syncthreads per tile.
// Plain loads (R5's __ldcs regressed); default stores.

constexpr int B_DIM  = 16;
constexpr int C_DIM  = 256;
constexpr int S_DIM  = 128 * 128;        // spatial per (b,c)
constexpr int GROUPS = 32;               // channel groups
constexpr int CPT    = C_DIM / GROUPS;   // 8 channels per thread
constexpr int LANES  = 8;                // float4 lanes per group
constexpr int VEC    = 4;
constexpr int SPB    = LANES * VEC;      // 32 spatial positions per tile
constexpr int THREADS = GROUPS * LANES;  // 256
constexpr int TILES_PER_B = S_DIM / SPB; // 512
constexpr int TILES_TOTAL = B_DIM * TILES_PER_B; // 8192
constexpr int GRID = 444;                // 3 blocks/SM * 148 SMs

constexpr long long CH_STRIDE4 = S_DIM / 4;  // channel stride in float4s

__device__ __forceinline__ long long tile_base4(int id, int grp, int lane)
{
    // flat tile id -> float4 index of this thread's first element
    const int b    = id >> 9;            // id / 512
    const int tile = id & 511;
    return ((long long)b * C_DIM * S_DIM
            + (long long)grp * CPT * S_DIM
            + (long long)tile * SPB) / 4 + lane;
}

__global__ __launch_bounds__(THREADS, 3)
void neighbour_channels_kernel(const float* __restrict__ x,
                               float* __restrict__ out)
{
    __shared__ float4 red[2][GROUPS][LANES];

    const int lane = threadIdx.x & (LANES - 1);
    const int grp  = threadIdx.x >> 3;

    const float4* __restrict__ xp4 = (const float4*)x;
    float4* __restrict__ op4 = (float4*)out;

    int id = blockIdx.x;                 // current tile
    if (id >= TILES_TOTAL) return;

    // Prologue: load tile `id` into v.
    float4 v[CPT];
    {
        const long long base4 = tile_base4(id, grp, lane);
#pragma unroll
        for (int i = 0; i < CPT; ++i)
            v[i] = xp4[base4 + (long long)i * CH_STRIDE4];
    }

    int parity = 0;
    while (true) {
        const int next = id + GRID;
        const bool has_next = (next < TILES_TOTAL);

        // Prefetch next tile's loads FIRST (max latency hiding).
        float4 vn[CPT];
        if (has_next) {
            const long long nbase4 = tile_base4(next, grp, lane);
#pragma unroll
            for (int i = 0; i < CPT; ++i)
                vn[i] = xp4[nbase4 + (long long)i * CH_STRIDE4];
        }

        // Reduce current tile.
        float4 sum = make_float4(0.f, 0.f, 0.f, 0.f);
#pragma unroll
        for (int i = 0; i < CPT; ++i) {
            sum.x += v[i].x; sum.y += v[i].y;
            sum.z += v[i].z; sum.w += v[i].w;
        }
        red[parity][grp][lane] = sum;
        __syncthreads();

        float4 total = make_float4(0.f, 0.f, 0.f, 0.f);
#pragma unroll
        for (int g = 0; g < GROUPS; ++g) {
            float4 p = red[parity][g][lane];
            total.x += p.x; total.y += p.y;
            total.z += p.z; total.w += p.w;
        }

        // Store current tile from registers.
        {
            const long long base4 = tile_base4(id, grp, lane);
#pragma unroll
            for (int i = 0; i < CPT; ++i) {
                float4 o;
                o.x = total.x - v[i].x;
                o.y = total.y - v[i].y;
                o.z = total.z - v[i].z;
                o.w = total.w - v[i].w;
                op4[base4 + (long long)i * CH_STRIDE4] = o;
            }
        }

        if (!has_next) break;
#pragma unroll
        for (int i = 0; i < CPT; ++i) v[i] = vn[i];
        id = next;
        parity ^= 1;
    }
}

extern "C" void kernel_launch(void* const* d_in, const int* in_sizes, int n_in,
                              void* d_out, int out_size)
{
    const float* x = (const float*)d_in[0];
    float* out = (float*)d_out;
    neighbour_channels_kernel<<<GRID, THREADS>>>(x, out);
}

// round 7
// speedup vs baseline: 1.1847x; 1.1847x over previous
#include <cuda_runtime.h>

// out[b,i,h,w] = sum_j x[b,j,h,w] - x[b,i,h,w]
// x: fp32 [16, 256, 128, 128]
//
// R7: max memory-level parallelism test. 256-thread blocks, CPT=16 channels
// x float4 (64 payload regs), 3 blocks/SM => ~196 KB of reads in flight per
// SM (1.5x the 131 KB of R2/R4 which both pinned at 6.11 TB/s). Tests whether
// the 6.1 TB/s plateau is a read-queue-depth limit (this wins) or the mixed
// read/write HBM turnaround ceiling (this ties).
// Reg budget: 65536/768 = 85/thread; payload 64 + ~16 overhead fits.

constexpr int B_DIM  = 16;
constexpr int C_DIM  = 256;
constexpr int S_DIM  = 128 * 128;        // spatial per (b,c)
constexpr int GROUPS = 16;               // channel groups per block
constexpr int CPT    = C_DIM / GROUPS;   // 16 channels per thread
constexpr int LANES  = 16;               // float4 lanes per group
constexpr int VEC    = 4;                // floats per lane (float4)
constexpr int SPB    = LANES * VEC;      // 64 spatial positions per block
constexpr int THREADS = GROUPS * LANES;  // 256

__global__ __launch_bounds__(THREADS, 3)
void neighbour_channels_kernel(const float* __restrict__ x,
                               float* __restrict__ out)
{
    __shared__ float4 red[GROUPS][LANES];

    const int lane = threadIdx.x & (LANES - 1);
    const int grp  = threadIdx.x >> 4;           // 0..15

    const int tiles_per_b = S_DIM / SPB;         // 256
    const int tile = blockIdx.x % tiles_per_b;
    const int b    = blockIdx.x / tiles_per_b;

    const long long spatial = (long long)tile * SPB + lane * VEC;
    const long long base    = (long long)b * C_DIM * S_DIM
                            + (long long)grp * CPT * S_DIM
                            + spatial;

    const float4* __restrict__ xp = (const float4*)(x + base);

    // 16 independent LDG.128 per thread -> deep read queue.
    float4 v[CPT];
#pragma unroll
    for (int i = 0; i < CPT; ++i) {
        v[i] = xp[(long long)i * (S_DIM / 4)];
    }

    float4 sum = make_float4(0.0f, 0.0f, 0.0f, 0.0f);
#pragma unroll
    for (int i = 0; i < CPT; ++i) {
        sum.x += v[i].x;
        sum.y += v[i].y;
        sum.z += v[i].z;
        sum.w += v[i].w;
    }

    // Cross-group reduction: 16 partials per lane.
    red[grp][lane] = sum;
    __syncthreads();

    float4 total = make_float4(0.0f, 0.0f, 0.0f, 0.0f);
#pragma unroll
    for (int g = 0; g < GROUPS; ++g) {
        float4 p = red[g][lane];
        total.x += p.x;
        total.y += p.y;
        total.z += p.z;
        total.w += p.w;
    }

    // Write out = total - x from registers (no second global read).
    float4* __restrict__ op = (float4*)(out + base);
#pragma unroll
    for (int i = 0; i < CPT; ++i) {
        float4 o;
        o.x = total.x - v[i].x;
        o.y = total.y - v[i].y;
        o.z = total.z - v[i].z;
        o.w = total.w - v[i].w;
        op[(long long)i * (S_DIM / 4)] = o;
    }
}

extern "C" void kernel_launch(void* const* d_in, const int* in_sizes, int n_in,
                              void* d_out, int out_size)
{
    const float* x = (const float*)d_in[0];
    float* out = (float*)d_out;

    const int grid = B_DIM * (S_DIM / SPB);  // 16 * 256 = 4096 blocks
    neighbour_channels_kernel<<<grid, THREADS>>>(x, out);
}

// round 8
// speedup vs baseline: 1.1883x; 1.0031x over previous
#include <cuda_runtime.h>

// out[b,i,h,w] = sum_j x[b,j,h,w] - x[b,i,h,w]
// x: fp32 [16, 256, 128, 128]
//
// R8 = R7 (CPT=16 x float4, 256-thread blocks, 3 blocks/SM, ~196 KB reads in
// flight per SM) + __stcs streaming stores. Steady-state graph replay starts
// each iteration with L2 full of the previous iteration's dirty output;
// evict-first stores drain writes promptly instead of piling writebacks into
// the next replay's read phase. Reads stay default (R5 showed __ldcs on the
// read side regresses).

constexpr int B_DIM  = 16;
constexpr int C_DIM  = 256;
constexpr int S_DIM  = 128 * 128;        // spatial per (b,c)
constexpr int GROUPS = 16;               // channel groups per block
constexpr int CPT    = C_DIM / GROUPS;   // 16 channels per thread
constexpr int LANES  = 16;               // float4 lanes per group
constexpr int VEC    = 4;                // floats per lane (float4)
constexpr int SPB    = LANES * VEC;      // 64 spatial positions per block
constexpr int THREADS = GROUPS * LANES;  // 256

__global__ __launch_bounds__(THREADS, 3)
void neighbour_channels_kernel(const float* __restrict__ x,
                               float* __restrict__ out)
{
    __shared__ float4 red[GROUPS][LANES];

    const int lane = threadIdx.x & (LANES - 1);
    const int grp  = threadIdx.x >> 4;           // 0..15

    const int tiles_per_b = S_DIM / SPB;         // 256
    const int tile = blockIdx.x % tiles_per_b;
    const int b    = blockIdx.x / tiles_per_b;

    const long long spatial = (long long)tile * SPB + lane * VEC;
    const long long base    = (long long)b * C_DIM * S_DIM
                            + (long long)grp * CPT * S_DIM
                            + spatial;

    const float4* __restrict__ xp = (const float4*)(x + base);

    // 16 independent LDG.128 per thread -> deep read queue.
    float4 v[CPT];
#pragma unroll
    for (int i = 0; i < CPT; ++i) {
        v[i] = xp[(long long)i * (S_DIM / 4)];
    }

    float4 sum = make_float4(0.0f, 0.0f, 0.0f, 0.0f);
#pragma unroll
    for (int i = 0; i < CPT; ++i) {
        sum.x += v[i].x;
        sum.y += v[i].y;
        sum.z += v[i].z;
        sum.w += v[i].w;
    }

    // Cross-group reduction: 16 partials per lane.
    red[grp][lane] = sum;
    __syncthreads();

    float4 total = make_float4(0.0f, 0.0f, 0.0f, 0.0f);
#pragma unroll
    for (int g = 0; g < GROUPS; ++g) {
        float4 p = red[g][lane];
        total.x += p.x;
        total.y += p.y;
        total.z += p.z;
        total.w += p.w;
    }

    // Streaming (evict-first) stores: drain writes promptly, keep L2 for reads.
    float4* __restrict__ op = (float4*)(out + base);
#pragma unroll
    for (int i = 0; i < CPT; ++i) {
        float4 o;
        o.x = total.x - v[i].x;
        o.y = total.y - v[i].y;
        o.z = total.z - v[i].z;
        o.w = total.w - v[i].w;
        __stcs(op + (long long)i * (S_DIM / 4), o);
    }
}

extern "C" void kernel_launch(void* const* d_in, const int* in_sizes, int n_in,
                              void* d_out, int out_size)
{
    const float* x = (const float*)d_in[0];
    float* out = (float*)d_out;

    const int grid = B_DIM * (S_DIM / SPB);  // 16 * 256 = 4096 blocks
    neighbour_channels_kernel<<<grid, THREADS>>>(x, out);
}